// round 12
// baseline (speedup 1.0000x reference)
#include <cuda_runtime.h>

// DeconvDft2dLayer == per-row 512-pt circular deconvolution:
//   y[row,:] = ifft( M(k) * fft(x[row,:]) ),  M(k) = 1/|H(k)|^4 (real),
//   H(k) = sum_{n=0}^{7} w[n] e^{-2pi i k n/512}.
// Two real rows packed per complex FFT (M real => exact).
// 512 = 16 x 32: 16 threads/FFT, one smem transpose per direction.
// Inverse via conj trick; inter-pass spectrum permute staged through the
// idle smem buffer (true data peak ~100 regs). Warp-synchronous.
// __launch_bounds__(64, 8): cap regs at 128 (above the ~100 natural peak,
// so spill-free) to double RF-limited occupancy vs the uncapped 168-reg build.

#define NW 512
#define NFB 4                    // FFTs per block (8 rows)
#define THREADS 64               // 16 threads per FFT
#define SROW 17                  // padded row (float2) for conflict-free transpose
#define SBUF (32 * SROW)         // 544 float2 per FFT

__device__ float d_M[NW];        // M(k)/512  (ifft 1/N folded in)

__global__ void compute_M_kernel(const float* __restrict__ w) {
    int k = threadIdx.x;
    float hr = 0.0f, hi = 0.0f;
#pragma unroll
    for (int n = 0; n < 8; n++) {
        int t = (k * n) & (NW - 1);          // exact integer phase
        float s, c;
        sincospif(-(float)t * (2.0f / NW), &s, &c);
        hr = fmaf(w[n], c, hr);
        hi = fmaf(w[n], s, hi);
    }
    float p = hr * hr + hi * hi;             // |H|^2
    d_M[k] = 1.0f / (p * p * (float)NW);
}

__device__ __forceinline__ float2 cmulf(float2 a, float2 b) {
    return make_float2(a.x * b.x - a.y * b.y, a.x * b.y + a.y * b.x);
}

// cos/sin(2*pi*j/32), j = 0..15 (compile-time switch).
__device__ __forceinline__ constexpr float c32(int j) {
    switch (j) {
        case 0:  return 1.0f;
        case 1:  return 0.9807852804032304491f;
        case 2:  return 0.9238795325112867561f;
        case 3:  return 0.8314696123025452371f;
        case 4:  return 0.7071067811865475244f;
        case 5:  return 0.5555702330196022248f;
        case 6:  return 0.3826834323650897717f;
        case 7:  return 0.1950903220161282678f;
        case 8:  return 0.0f;
        case 9:  return -0.1950903220161282678f;
        case 10: return -0.3826834323650897717f;
        case 11: return -0.5555702330196022248f;
        case 12: return -0.7071067811865475244f;
        case 13: return -0.8314696123025452371f;
        case 14: return -0.9238795325112867561f;
        default: return -0.9807852804032304491f;
    }
}
__device__ __forceinline__ constexpr float s32(int j) {
    switch (j) {
        case 0:  return 0.0f;
        case 1:  return 0.1950903220161282678f;
        case 2:  return 0.3826834323650897717f;
        case 3:  return 0.5555702330196022248f;
        case 4:  return 0.7071067811865475244f;
        case 5:  return 0.8314696123025452371f;
        case 6:  return 0.9238795325112867561f;
        case 7:  return 0.9807852804032304491f;
        case 8:  return 1.0f;
        case 9:  return 0.9807852804032304491f;
        case 10: return 0.9238795325112867561f;
        case 11: return 0.8314696123025452371f;
        case 12: return 0.7071067811865475244f;
        case 13: return 0.5555702330196022248f;
        case 14: return 0.3826834323650897717f;
        default: return 0.1950903220161282678f;
    }
}

__device__ __forceinline__ constexpr int brev(int p, int nb) {
    int r = 0;
    for (int i = 0; i < nb; i++) { r = (r << 1) | (p & 1); p >>= 1; }
    return r;
}

// Fully-unrolled radix-2 DIF FFT, size N (<=32). Natural input; output
// bit-reversed: reg p = X[brev(p, log2 N)]. Forward kernel e^{-i...}.
template<int N>
__device__ __forceinline__ void fft_dif(float* __restrict__ xr,
                                        float* __restrict__ xi) {
#pragma unroll
    for (int m = N / 2; m >= 1; m >>= 1) {
#pragma unroll
        for (int g = 0; g < N; g += 2 * m) {
#pragma unroll
            for (int j = 0; j < m; j++) {
                int a = g + j, b = g + j + m;
                float ur = xr[a], ui = xi[a];
                float vr = xr[b], vi = xi[b];
                xr[a] = ur + vr;
                xi[a] = ui + vi;
                float dr = ur - vr, di = ui - vi;
                float wc = c32(j * 16 / m);   // W_{2m}^j = e^{-2pi i j/(2m)}
                float ws = s32(j * 16 / m);
                xr[b] = dr * wc + di * ws;    // (dr+i di)*(wc - i ws)
                xi[b] = di * wc - dr * ws;
            }
        }
    }
}

// Stage-1 twiddle + transposed store: rows t and t+16, bases w0, w1.
// Powers built in 4 chunks of 4 (dependency depth ~6 instead of 15).
__device__ __forceinline__ void tw_transpose(float2* __restrict__ S,
                                             const float ar[2][16],
                                             const float ai[2][16],
                                             float2 w0, float2 w1, int t) {
    float2 w0sq = cmulf(w0, w0);
    float2 w1sq = cmulf(w1, w1);
    float2 w0_4 = cmulf(w0sq, w0sq);
    float2 w1_4 = cmulf(w1sq, w1sq);
    float2 base0 = make_float2(1.0f, 0.0f);
    float2 base1 = make_float2(1.0f, 0.0f);
#pragma unroll
    for (int a = 0; a < 4; a++) {
        float2 p0 = base0, p1 = base1;
#pragma unroll
        for (int c = 0; c < 4; c++) {
            int k2 = 4 * a + c;
            int pos = brev(k2, 4);
            S[t * SROW + k2] = make_float2(ar[0][pos] * p0.x - ai[0][pos] * p0.y,
                                           ar[0][pos] * p0.y + ai[0][pos] * p0.x);
            S[(t + 16) * SROW + k2] = make_float2(ar[1][pos] * p1.x - ai[1][pos] * p1.y,
                                                  ar[1][pos] * p1.y + ai[1][pos] * p1.x);
            if (c < 3) { p0 = cmulf(p0, w0); p1 = cmulf(p1, w1); }
        }
        if (a < 3) { base0 = cmulf(base0, w0_4); base1 = cmulf(base1, w1_4); }
    }
}

__global__ void __launch_bounds__(THREADS, 8)
fft_conv_kernel(const float* __restrict__ x, float* __restrict__ out) {
    __shared__ float2 sX[NFB][SBUF];

    int tid = threadIdx.x;
    int f = tid >> 4;       // FFT within block
    int t = tid & 15;       // lane within FFT (n1 mod 16 / k2)
    float2* S = sX[f];

    long long row0 = ((long long)blockIdx.x * NFB + f) * 2;
    const float* x0 = x + row0 * NW;
    const float* x1 = x0 + NW;

    // Twiddle bases: b0 = W^t, b1 = W^{t+16}, W = e^{-2pi i/512}.
    float2 b0, b1;
    sincospif(-(float)t * (1.0f / 256.0f), &b0.y, &b0.x);
    {
        const float wsr = 0.9807852804032304491f;    // cos(2pi*16/512)
        const float wsi = -0.1950903220161282678f;   // -sin(2pi*16/512)
        b1 = make_float2(b0.x * wsr - b0.y * wsi, b0.x * wsi + b0.y * wsr);
    }

    // ---- pass 0 (forward), stage 1: FFT16 over n2; n = t + 16b + 32n2 ----
    {
        float ar[2][16], ai[2][16];
#pragma unroll
        for (int b = 0; b < 2; b++)
#pragma unroll
            for (int n2 = 0; n2 < 16; n2++) {
                int n = t + 16 * b + 32 * n2;
                ar[b][n2] = __ldg(x0 + n);
                ai[b][n2] = __ldg(x1 + n);
            }
        fft_dif<16>(ar[0], ai[0]);
        fft_dif<16>(ar[1], ai[1]);
        tw_transpose(S, ar, ai, b0, b1, t);
    }
    __syncwarp();

    // ---- pass 0, stage 2: FFT32 over n1 for k2 = t ----
    {
        float cr[32], ci[32];
#pragma unroll
        for (int n1 = 0; n1 < 32; n1++) {
            float2 v = S[n1 * SROW + t];
            cr[n1] = v.x;
            ci[n1] = v.y;
        }
        __syncwarp();           // all reads done before overwrite below

        fft_dif<32>(cr, ci);    // reg p = X[t + 16*brev(p,5)]

        // Stage g[k] = conj(M*X[k]) through S in pass-1 input layout.
#pragma unroll
        for (int p = 0; p < 32; p++) {
            int k = t + 16 * brev(p, 5);
            float m = __ldg(&d_M[k]);
            S[k] = make_float2(cr[p] * m, -ci[p] * m);
        }
    }
    __syncwarp();

    // ---- pass 1 (forward pipeline on g; conj trick), stage 1 ----
    {
        float ar[2][16], ai[2][16];
#pragma unroll
        for (int b = 0; b < 2; b++)
#pragma unroll
            for (int n2 = 0; n2 < 16; n2++) {
                float2 v = S[t + 16 * b + 32 * n2];
                ar[b][n2] = v.x;
                ai[b][n2] = v.y;
            }
        __syncwarp();           // reads done before transpose store

        fft_dif<16>(ar[0], ai[0]);
        fft_dif<16>(ar[1], ai[1]);
        tw_transpose(S, ar, ai, b0, b1, t);
    }
    __syncwarp();

    // ---- pass 1, stage 2 + output ----
    {
        float cr[32], ci[32];
#pragma unroll
        for (int n1 = 0; n1 < 32; n1++) {
            float2 v = S[n1 * SROW + t];
            cr[n1] = v.x;
            ci[n1] = v.y;
        }

        fft_dif<32>(cr, ci);    // reg p = Ghat[n = t + 16*brev(p,5)]

        // y = conj(Ghat) (1/512 folded into M): re -> row0, -im -> row1.
        float* o0 = out + row0 * NW;
        float* o1 = o0 + NW;
#pragma unroll
        for (int p = 0; p < 32; p++) {
            int n = t + 16 * brev(p, 5);
            o0[n] = cr[p];
            o1[n] = -ci[p];
        }
    }
}

extern "C" void kernel_launch(void* const* d_in, const int* in_sizes, int n_in,
                              void* d_out, int out_size) {
    const float* x = (const float*)d_in[0];
    const float* w = (const float*)d_in[1];
    if (n_in >= 2 && in_sizes[0] < in_sizes[1]) {   // defensive: x is the big one
        const float* t = x; x = w; w = t;
    }
    float* out = (float*)d_out;

    compute_M_kernel<<<1, NW>>>(w);

    int rows = out_size / NW;          // 16384
    int blocks = rows / (2 * NFB);     // 2048 (8 rows per block)
    fft_conv_kernel<<<blocks, THREADS>>>(x, out);
}

// round 13
// speedup vs baseline: 1.0015x; 1.0015x over previous
#include <cuda_runtime.h>

// DeconvDft2dLayer == per-row 512-pt circular deconvolution:
//   y[row,:] = ifft( M(k) * fft(x[row,:]) ),  M(k) = 1/|H(k)|^4 (real),
//   H(k) = sum_{n=0}^{7} w[n] e^{-2pi i k n/512}.
// Two real rows packed per complex FFT (M real => exact). Each thread runs
// TWO independent FFTs (4 rows) packed element-wise into f32x2 registers:
// every butterfly/twiddle/M op is ONE packed instruction (FFMA2) for both
// FFTs. Radix-8 Stockham, ping-pong padded smem, 4 block syncs.

#define NW 512
#define THREADS 64
#define PADN (NW + (NW >> 3))   // 576 u64 entries per component buffer

typedef unsigned long long u64;

__device__ float d_M[NW];        // M(k)/512  (ifft 1/N folded in)

__global__ void compute_M_kernel(const float* __restrict__ w) {
    int k = threadIdx.x;
    float hr = 0.0f, hi = 0.0f;
#pragma unroll
    for (int n = 0; n < 8; n++) {
        int t = (k * n) & (NW - 1);
        float s, c;
        sincospif(-(float)t * (2.0f / NW), &s, &c);
        hr = fmaf(w[n], c, hr);
        hi = fmaf(w[n], s, hi);
    }
    float p = hr * hr + hi * hi;
    d_M[k] = 1.0f / (p * p * (float)NW);
}

// ---- packed f32x2 primitives (Blackwell sm_100+) ----
__device__ __forceinline__ u64 pk2(float lo, float hi) {
    u64 r; asm("mov.b64 %0, {%1, %2};" : "=l"(r) : "f"(lo), "f"(hi)); return r;
}
__device__ __forceinline__ u64 pbc(float v) { return pk2(v, v); }
__device__ __forceinline__ void upk2(u64 a, float& lo, float& hi) {
    asm("mov.b64 {%0, %1}, %2;" : "=f"(lo), "=f"(hi) : "l"(a));
}
__device__ __forceinline__ u64 padd(u64 a, u64 b) {
    u64 r; asm("add.rn.f32x2 %0, %1, %2;" : "=l"(r) : "l"(a), "l"(b)); return r;
}
__device__ __forceinline__ u64 pmul(u64 a, u64 b) {
    u64 r; asm("mul.rn.f32x2 %0, %1, %2;" : "=l"(r) : "l"(a), "l"(b)); return r;
}
__device__ __forceinline__ u64 pfma(u64 a, u64 b, u64 c) {   // a*b + c
    u64 r; asm("fma.rn.f32x2 %0, %1, %2, %3;" : "=l"(r) : "l"(a), "l"(b), "l"(c)); return r;
}

__device__ __forceinline__ float2 cmulf(float2 a, float2 b) {
    return make_float2(a.x * b.x - a.y * b.y, a.x * b.y + a.y * b.x);
}

// Packed radix-8 DFT: one instruction stream computes both packed FFTs.
template<bool INV>
__device__ __forceinline__ void dft8p(u64* zr, u64* zi) {
    const float sf = INV ? 1.0f : -1.0f;
    const u64 N1 = pbc(-1.0f);
    const u64 S  = pbc(sf);
    const u64 NS = pbc(-sf);
    const u64 CC = pbc(0.70710678118654752440f);
    const u64 NC = pbc(-0.70710678118654752440f);

    u64 e0r = padd(zr[0], zr[4]),     e0i = padd(zi[0], zi[4]);
    u64 e1r = pfma(zr[4], N1, zr[0]), e1i = pfma(zi[4], N1, zi[0]);
    u64 e2r = padd(zr[2], zr[6]),     e2i = padd(zi[2], zi[6]);
    u64 e3r = pfma(zr[6], N1, zr[2]), e3i = pfma(zi[6], N1, zi[2]);
    u64 E0r = padd(e0r, e2r),         E0i = padd(e0i, e2i);
    u64 E2r = pfma(e2r, N1, e0r),     E2i = pfma(e2i, N1, e0i);
    u64 E1r = pfma(e3i, NS, e1r),     E1i = pfma(e3r, S, e1i);   // e1 + s*i*e3
    u64 E3r = pfma(e3i, S, e1r),      E3i = pfma(e3r, NS, e1i);

    u64 o0r = padd(zr[1], zr[5]),     o0i = padd(zi[1], zi[5]);
    u64 o1r = pfma(zr[5], N1, zr[1]), o1i = pfma(zi[5], N1, zi[1]);
    u64 o2r = padd(zr[3], zr[7]),     o2i = padd(zi[3], zi[7]);
    u64 o3r = pfma(zr[7], N1, zr[3]), o3i = pfma(zi[7], N1, zi[3]);
    u64 O0r = padd(o0r, o2r),         O0i = padd(o0i, o2i);
    u64 O2r = pfma(o2r, N1, o0r),     O2i = pfma(o2i, N1, o0i);
    u64 O1r = pfma(o3i, NS, o1r),     O1i = pfma(o3r, S, o1i);
    u64 O3r = pfma(o3i, S, o1r),      O3i = pfma(o3r, NS, o1i);

    // w8^1 = C*(1 + s*i); w8^2 = s*i; w8^3 = C*(-1 + s*i)
    u64 w1r = pmul(CC, pfma(O1i, NS, O1r));   //  C*(O1r - s*O1i)
    u64 w1i = pmul(CC, pfma(O1r, S,  O1i));   //  C*(s*O1r + O1i)
    u64 w2r = pmul(O2i, NS);                  // -s*O2i
    u64 w2i = pmul(O2r, S);                   //  s*O2r
    u64 w3r = pmul(NC, pfma(O3i, S,  O3r));   //  C*(-O3r - s*O3i)
    u64 w3i = pmul(NC, pfma(O3r, NS, O3i));   //  C*( s*O3r - O3i)

    zr[0] = padd(E0r, w1r * 0 + O0r); zi[0] = padd(E0i, O0i);
    zr[0] = padd(E0r, O0r);
    zr[4] = pfma(O0r, N1, E0r);       zi[4] = pfma(O0i, N1, E0i);
    zr[1] = padd(E1r, w1r);           zi[1] = padd(E1i, w1i);
    zr[5] = pfma(w1r, N1, E1r);       zi[5] = pfma(w1i, N1, E1i);
    zr[2] = padd(E2r, w2r);           zi[2] = padd(E2i, w2i);
    zr[6] = pfma(w2r, N1, E2r);       zi[6] = pfma(w2i, N1, E2i);
    zr[3] = padd(E3r, w3r);           zi[3] = padd(E3i, w3i);
    zr[7] = pfma(w3r, N1, E3r);       zi[7] = pfma(w3i, N1, E3i);
}

// Twiddle by W^j (conj for INV) and store packed components; scalar power
// table built once with a log-depth chain, broadcast at use.
template<bool INV>
__device__ __forceinline__ void tw_storep(u64* __restrict__ bre, u64* __restrict__ bim,
                                          const u64* zr, const u64* zi,
                                          float2 w, int base, int stride) {
    bre[base] = zr[0];
    bim[base] = zi[0];
    float2 cs[8];
    cs[1] = w;
    cs[2] = cmulf(w, w);
    cs[3] = cmulf(cs[2], w);
    cs[4] = cmulf(cs[2], cs[2]);
    cs[5] = cmulf(cs[4], w);
    cs[6] = cmulf(cs[4], cs[2]);
    cs[7] = cmulf(cs[4], cs[3]);
#pragma unroll
    for (int j = 1; j < 8; j++) {
        float cr = cs[j].x;
        float ci = INV ? -cs[j].y : cs[j].y;
        u64 R  = pbc(cr);
        u64 I  = pbc(ci);
        u64 NI = pbc(-ci);
        int idx = base + stride * j;
        bre[idx] = pfma(zi[j], NI, pmul(zr[j], R));   // zr*cr - zi*ci
        bim[idx] = pfma(zr[j], I,  pmul(zi[j], R));   // zr*ci + zi*cr
    }
}

__device__ __forceinline__ void loadp(u64* zr, u64* zi,
                                      const u64* __restrict__ bre,
                                      const u64* __restrict__ bim, int ub) {
#pragma unroll
    for (int j = 0; j < 8; j++) {
        zr[j] = bre[ub + 72 * j];
        zi[j] = bim[ub + 72 * j];
    }
}

__global__ void __launch_bounds__(THREADS, 8)
fft_conv_kernel(const float* __restrict__ x, float* __restrict__ out) {
    __shared__ u64 sPr[PADN], sPi[PADN];   // ping (packed re, packed im)
    __shared__ u64 sQr[PADN], sQi[PADN];   // pong

    int u = threadIdx.x;
    int ub = u + (u >> 3);
    int p = u >> 3, q = u & 7;

    float2 w1, w2;
    sincospif(-(float)u * (1.0f / 256.0f), &w1.y, &w1.x);   // e^{-2pi i u/512}
    sincospif(-(float)p * (1.0f / 32.0f),  &w2.y, &w2.x);   // e^{-2pi i p/64}

    int base = blockIdx.x * (4 * NW);   // 4 rows per block
    const float* xA0 = x + base;
    const float* xA1 = xA0 + NW;
    const float* xB0 = xA0 + 2 * NW;
    const float* xB1 = xA0 + 3 * NW;

    // Packed registers: lane0 = FFT A (rows 0,1), lane1 = FFT B (rows 2,3).
    u64 zr[8], zi[8];
#pragma unroll
    for (int j = 0; j < 8; j++) {
        int g = u + 64 * j;
        zr[j] = pk2(__ldg(xA0 + g), __ldg(xB0 + g));
        zi[j] = pk2(__ldg(xA1 + g), __ldg(xB1 + g));
    }

    // ---- forward ----
    dft8p<false>(zr, zi);
    tw_storep<false>(sPr, sPi, zr, zi, w1, 9 * u, 1);
    __syncthreads();

    loadp(zr, zi, sPr, sPi, ub);
    dft8p<false>(zr, zi);
    tw_storep<false>(sQr, sQi, zr, zi, w2, q + 72 * p, 9);
    __syncthreads();

    loadp(zr, zi, sQr, sQi, ub);
    dft8p<false>(zr, zi);               // natural order: reg j = bin u+64j

    // ---- spectrum multiply by real M (broadcast to both lanes) ----
#pragma unroll
    for (int j = 0; j < 8; j++) {
        u64 m = pbc(__ldg(&d_M[u + 64 * j]));
        zr[j] = pmul(zr[j], m);
        zi[j] = pmul(zi[j], m);
    }

    // ---- inverse ---- (ping-pong: sP reads all completed before sync2)
    dft8p<true>(zr, zi);
    tw_storep<true>(sPr, sPi, zr, zi, w1, 9 * u, 1);
    __syncthreads();

    loadp(zr, zi, sPr, sPi, ub);
    dft8p<true>(zr, zi);
    tw_storep<true>(sQr, sQi, zr, zi, w2, q + 72 * p, 9);
    __syncthreads();

    loadp(zr, zi, sQr, sQi, ub);
    dft8p<true>(zr, zi);

    float* oA0 = out + base;
    float* oA1 = oA0 + NW;
    float* oB0 = oA0 + 2 * NW;
    float* oB1 = oA0 + 3 * NW;
#pragma unroll
    for (int j = 0; j < 8; j++) {
        int g = u + 64 * j;
        float a, b;
        upk2(zr[j], a, b);
        oA0[g] = a;
        oB0[g] = b;
        upk2(zi[j], a, b);
        oA1[g] = a;
        oB1[g] = b;
    }
}

extern "C" void kernel_launch(void* const* d_in, const int* in_sizes, int n_in,
                              void* d_out, int out_size) {
    const float* x = (const float*)d_in[0];
    const float* w = (const float*)d_in[1];
    if (n_in >= 2 && in_sizes[0] < in_sizes[1]) {   // defensive: x is the big one
        const float* t = x; x = w; w = t;
    }
    float* out = (float*)d_out;

    compute_M_kernel<<<1, NW>>>(w);

    int rows = out_size / NW;        // 16384
    int blocks = rows / 4;           // 4096 (4 rows per block)
    fft_conv_kernel<<<blocks, THREADS>>>(x, out);
}

// round 14
// speedup vs baseline: 1.1085x; 1.1068x over previous
#include <cuda_runtime.h>

// DeconvDft2dLayer == per-row 512-pt circular deconvolution:
//   y[row,:] = ifft( M(k) * fft(x[row,:]) ),  M(k) = 1/|H(k)|^4 (real),
//   H(k) = sum_{n=0}^{7} w[n] e^{-2pi i k n/512}.
// Two real rows packed per complex FFT (M real => exact). Each thread runs
// TWO independent FFTs (4 rows) packed element-wise into f32x2 registers
// (FFMA2: one packed instruction per butterfly op for both FFTs).
// Radix-8 Stockham, ping-pong smem of 16B ulonglong2 (re,im packed) ->
// LDS.128/STS.128 halves the smem instruction count; padded conflict-free.

#define NW 512
#define THREADS 64
#define PADN (NW + (NW >> 3))   // 576 ulonglong2 entries per buffer

typedef unsigned long long u64;

__device__ float d_M[NW];        // M(k)/512  (ifft 1/N folded in)

__global__ void compute_M_kernel(const float* __restrict__ w) {
    int k = blockIdx.x * 64 + threadIdx.x;   // 8 blocks x 64 threads
    float hr = 0.0f, hi = 0.0f;
#pragma unroll
    for (int n = 0; n < 8; n++) {
        int t = (k * n) & (NW - 1);
        float s, c;
        sincospif(-(float)t * (2.0f / NW), &s, &c);
        hr = fmaf(w[n], c, hr);
        hi = fmaf(w[n], s, hi);
    }
    float p = hr * hr + hi * hi;
    d_M[k] = 1.0f / (p * p * (float)NW);
}

// ---- packed f32x2 primitives (Blackwell sm_100+) ----
__device__ __forceinline__ u64 pk2(float lo, float hi) {
    u64 r; asm("mov.b64 %0, {%1, %2};" : "=l"(r) : "f"(lo), "f"(hi)); return r;
}
__device__ __forceinline__ u64 pbc(float v) { return pk2(v, v); }
__device__ __forceinline__ void upk2(u64 a, float& lo, float& hi) {
    asm("mov.b64 {%0, %1}, %2;" : "=f"(lo), "=f"(hi) : "l"(a));
}
__device__ __forceinline__ u64 padd(u64 a, u64 b) {
    u64 r; asm("add.rn.f32x2 %0, %1, %2;" : "=l"(r) : "l"(a), "l"(b)); return r;
}
__device__ __forceinline__ u64 pmul(u64 a, u64 b) {
    u64 r; asm("mul.rn.f32x2 %0, %1, %2;" : "=l"(r) : "l"(a), "l"(b)); return r;
}
__device__ __forceinline__ u64 pfma(u64 a, u64 b, u64 c) {   // a*b + c
    u64 r; asm("fma.rn.f32x2 %0, %1, %2, %3;" : "=l"(r) : "l"(a), "l"(b), "l"(c)); return r;
}

__device__ __forceinline__ float2 cmulf(float2 a, float2 b) {
    return make_float2(a.x * b.x - a.y * b.y, a.x * b.y + a.y * b.x);
}

// Packed radix-8 DFT: one instruction stream computes both packed FFTs.
template<bool INV>
__device__ __forceinline__ void dft8p(u64* zr, u64* zi) {
    const float sf = INV ? 1.0f : -1.0f;
    const u64 N1 = pbc(-1.0f);
    const u64 S  = pbc(sf);
    const u64 NS = pbc(-sf);
    const u64 CC = pbc(0.70710678118654752440f);
    const u64 NC = pbc(-0.70710678118654752440f);

    u64 e0r = padd(zr[0], zr[4]),     e0i = padd(zi[0], zi[4]);
    u64 e1r = pfma(zr[4], N1, zr[0]), e1i = pfma(zi[4], N1, zi[0]);
    u64 e2r = padd(zr[2], zr[6]),     e2i = padd(zi[2], zi[6]);
    u64 e3r = pfma(zr[6], N1, zr[2]), e3i = pfma(zi[6], N1, zi[2]);
    u64 E0r = padd(e0r, e2r),         E0i = padd(e0i, e2i);
    u64 E2r = pfma(e2r, N1, e0r),     E2i = pfma(e2i, N1, e0i);
    u64 E1r = pfma(e3i, NS, e1r),     E1i = pfma(e3r, S, e1i);   // e1 + s*i*e3
    u64 E3r = pfma(e3i, S, e1r),      E3i = pfma(e3r, NS, e1i);

    u64 o0r = padd(zr[1], zr[5]),     o0i = padd(zi[1], zi[5]);
    u64 o1r = pfma(zr[5], N1, zr[1]), o1i = pfma(zi[5], N1, zi[1]);
    u64 o2r = padd(zr[3], zr[7]),     o2i = padd(zi[3], zi[7]);
    u64 o3r = pfma(zr[7], N1, zr[3]), o3i = pfma(zi[7], N1, zi[3]);
    u64 O0r = padd(o0r, o2r),         O0i = padd(o0i, o2i);
    u64 O2r = pfma(o2r, N1, o0r),     O2i = pfma(o2i, N1, o0i);
    u64 O1r = pfma(o3i, NS, o1r),     O1i = pfma(o3r, S, o1i);
    u64 O3r = pfma(o3i, S, o1r),      O3i = pfma(o3r, NS, o1i);

    // w8^1 = C*(1 + s*i); w8^2 = s*i; w8^3 = C*(-1 + s*i)
    u64 w1r = pmul(CC, pfma(O1i, NS, O1r));   //  C*(O1r - s*O1i)
    u64 w1i = pmul(CC, pfma(O1r, S,  O1i));   //  C*(s*O1r + O1i)
    u64 w2r = pmul(O2i, NS);                  // -s*O2i
    u64 w2i = pmul(O2r, S);                   //  s*O2r
    u64 w3r = pmul(NC, pfma(O3i, S,  O3r));   //  C*(-O3r - s*O3i)
    u64 w3i = pmul(NC, pfma(O3r, NS, O3i));   //  C*( s*O3r - O3i)

    zr[0] = padd(E0r, O0r);           zi[0] = padd(E0i, O0i);
    zr[4] = pfma(O0r, N1, E0r);       zi[4] = pfma(O0i, N1, E0i);
    zr[1] = padd(E1r, w1r);           zi[1] = padd(E1i, w1i);
    zr[5] = pfma(w1r, N1, E1r);       zi[5] = pfma(w1i, N1, E1i);
    zr[2] = padd(E2r, w2r);           zi[2] = padd(E2i, w2i);
    zr[6] = pfma(w2r, N1, E2r);       zi[6] = pfma(w2i, N1, E2i);
    zr[3] = padd(E3r, w3r);           zi[3] = padd(E3i, w3i);
    zr[7] = pfma(w3r, N1, E3r);       zi[7] = pfma(w3i, N1, E3i);
}

// Twiddle by W^j (conj for INV) and store {re,im} as one 16B element; scalar
// power table built once with a log-depth chain, broadcast at use.
template<bool INV>
__device__ __forceinline__ void tw_storep(ulonglong2* __restrict__ buf,
                                          const u64* zr, const u64* zi,
                                          float2 w, int base, int stride) {
    buf[base] = make_ulonglong2(zr[0], zi[0]);
    float2 cs[8];
    cs[1] = w;
    cs[2] = cmulf(w, w);
    cs[3] = cmulf(cs[2], w);
    cs[4] = cmulf(cs[2], cs[2]);
    cs[5] = cmulf(cs[4], w);
    cs[6] = cmulf(cs[4], cs[2]);
    cs[7] = cmulf(cs[4], cs[3]);
#pragma unroll
    for (int j = 1; j < 8; j++) {
        float cr = cs[j].x;
        float ci = INV ? -cs[j].y : cs[j].y;
        u64 R  = pbc(cr);
        u64 I  = pbc(ci);
        u64 NI = pbc(-ci);
        int idx = base + stride * j;
        buf[idx] = make_ulonglong2(pfma(zi[j], NI, pmul(zr[j], R)),    // re
                                   pfma(zr[j], I,  pmul(zi[j], R)));   // im
    }
}

__device__ __forceinline__ void loadp(u64* zr, u64* zi,
                                      const ulonglong2* __restrict__ buf, int ub) {
#pragma unroll
    for (int j = 0; j < 8; j++) {
        ulonglong2 v = buf[ub + 72 * j];
        zr[j] = v.x;
        zi[j] = v.y;
    }
}

__global__ void __launch_bounds__(THREADS, 8)
fft_conv_kernel(const float* __restrict__ x, float* __restrict__ out) {
    __shared__ ulonglong2 sP[PADN];   // ping: {packed re, packed im}
    __shared__ ulonglong2 sQ[PADN];   // pong

    int u = threadIdx.x;
    int ub = u + (u >> 3);
    int p = u >> 3, q = u & 7;

    float2 w1, w2;
    sincospif(-(float)u * (1.0f / 256.0f), &w1.y, &w1.x);   // e^{-2pi i u/512}
    sincospif(-(float)p * (1.0f / 32.0f),  &w2.y, &w2.x);   // e^{-2pi i p/64}

    int base = blockIdx.x * (4 * NW);   // 4 rows per block
    const float* xA0 = x + base;
    const float* xA1 = xA0 + NW;
    const float* xB0 = xA0 + 2 * NW;
    const float* xB1 = xA0 + 3 * NW;

    // Packed registers: lane0 = FFT A (rows 0,1), lane1 = FFT B (rows 2,3).
    u64 zr[8], zi[8];
#pragma unroll
    for (int j = 0; j < 8; j++) {
        int g = u + 64 * j;
        zr[j] = pk2(__ldg(xA0 + g), __ldg(xB0 + g));
        zi[j] = pk2(__ldg(xA1 + g), __ldg(xB1 + g));
    }

    // ---- forward ----
    dft8p<false>(zr, zi);
    tw_storep<false>(sP, zr, zi, w1, 9 * u, 1);
    __syncthreads();

    loadp(zr, zi, sP, ub);
    dft8p<false>(zr, zi);
    tw_storep<false>(sQ, zr, zi, w2, q + 72 * p, 9);
    __syncthreads();

    loadp(zr, zi, sQ, ub);
    dft8p<false>(zr, zi);               // natural order: reg j = bin u+64j

    // ---- spectrum multiply by real M (broadcast to both lanes) ----
#pragma unroll
    for (int j = 0; j < 8; j++) {
        u64 m = pbc(__ldg(&d_M[u + 64 * j]));
        zr[j] = pmul(zr[j], m);
        zi[j] = pmul(zi[j], m);
    }

    // ---- inverse ---- (ping-pong: sP reads all completed before sync2)
    dft8p<true>(zr, zi);
    tw_storep<true>(sP, zr, zi, w1, 9 * u, 1);
    __syncthreads();

    loadp(zr, zi, sP, ub);
    dft8p<true>(zr, zi);
    tw_storep<true>(sQ, zr, zi, w2, q + 72 * p, 9);
    __syncthreads();

    loadp(zr, zi, sQ, ub);
    dft8p<true>(zr, zi);

    float* oA0 = out + base;
    float* oA1 = oA0 + NW;
    float* oB0 = oA0 + 2 * NW;
    float* oB1 = oA0 + 3 * NW;
#pragma unroll
    for (int j = 0; j < 8; j++) {
        int g = u + 64 * j;
        float a, b;
        upk2(zr[j], a, b);
        oA0[g] = a;
        oB0[g] = b;
        upk2(zi[j], a, b);
        oA1[g] = a;
        oB1[g] = b;
    }
}

extern "C" void kernel_launch(void* const* d_in, const int* in_sizes, int n_in,
                              void* d_out, int out_size) {
    const float* x = (const float*)d_in[0];
    const float* w = (const float*)d_in[1];
    if (n_in >= 2 && in_sizes[0] < in_sizes[1]) {   // defensive: x is the big one
        const float* t = x; x = w; w = t;
    }
    float* out = (float*)d_out;

    compute_M_kernel<<<8, 64>>>(w);   // spread MUFU work over 8 SMs

    int rows = out_size / NW;        // 16384
    int blocks = rows / 4;           // 4096 (4 rows per block)
    fft_conv_kernel<<<blocks, THREADS>>>(x, out);
}

// round 15
// speedup vs baseline: 1.1104x; 1.0017x over previous
#include <cuda_runtime.h>

// DeconvDft2dLayer == per-row 512-pt circular deconvolution:
//   y[row,:] = ifft( M(k) * fft(x[row,:]) ),  M(k) = 1/|H(k)|^4 (real),
//   H(k) = sum_{n=0}^{7} w[n] e^{-2pi i k n/512}.
// Two real rows packed per complex FFT (M real => exact). Each thread runs
// TWO independent FFTs (4 rows) packed element-wise into f32x2 registers
// (add/sub/mul/fma.rn.f32x2). Radix-8 Stockham, ping-pong smem of 16B
// ulonglong2 (LDS.128/STS.128), padded conflict-free. dft8 uses compile-time
// sign folding (no broadcast sign constants, adds/subs instead of FMAs).

#define NW 512
#define THREADS 64
#define PADN (NW + (NW >> 3))   // 576 ulonglong2 entries per buffer

typedef unsigned long long u64;

__device__ float d_M[NW];        // M(k)/512  (ifft 1/N folded in)

__global__ void compute_M_kernel(const float* __restrict__ w) {
    int k = blockIdx.x * 64 + threadIdx.x;   // 8 blocks x 64 threads
    float hr = 0.0f, hi = 0.0f;
#pragma unroll
    for (int n = 0; n < 8; n++) {
        int t = (k * n) & (NW - 1);
        float s, c;
        sincospif(-(float)t * (2.0f / NW), &s, &c);
        hr = fmaf(w[n], c, hr);
        hi = fmaf(w[n], s, hi);
    }
    float p = hr * hr + hi * hi;
    d_M[k] = 1.0f / (p * p * (float)NW);
}

// ---- packed f32x2 primitives (Blackwell sm_100+) ----
__device__ __forceinline__ u64 pk2(float lo, float hi) {
    u64 r; asm("mov.b64 %0, {%1, %2};" : "=l"(r) : "f"(lo), "f"(hi)); return r;
}
__device__ __forceinline__ u64 pbc(float v) { return pk2(v, v); }
__device__ __forceinline__ void upk2(u64 a, float& lo, float& hi) {
    asm("mov.b64 {%0, %1}, %2;" : "=f"(lo), "=f"(hi) : "l"(a));
}
__device__ __forceinline__ u64 padd(u64 a, u64 b) {
    u64 r; asm("add.rn.f32x2 %0, %1, %2;" : "=l"(r) : "l"(a), "l"(b)); return r;
}
__device__ __forceinline__ u64 psub(u64 a, u64 b) {
    u64 r; asm("sub.rn.f32x2 %0, %1, %2;" : "=l"(r) : "l"(a), "l"(b)); return r;
}
__device__ __forceinline__ u64 pmul(u64 a, u64 b) {
    u64 r; asm("mul.rn.f32x2 %0, %1, %2;" : "=l"(r) : "l"(a), "l"(b)); return r;
}
__device__ __forceinline__ u64 pfma(u64 a, u64 b, u64 c) {   // a*b + c
    u64 r; asm("fma.rn.f32x2 %0, %1, %2, %3;" : "=l"(r) : "l"(a), "l"(b), "l"(c)); return r;
}

__device__ __forceinline__ float2 cmulf(float2 a, float2 b) {
    return make_float2(a.x * b.x - a.y * b.y, a.x * b.y + a.y * b.x);
}

// Packed radix-8 DFT with compile-time sign folding. Forward: s = -1 (e^{-i}),
// INV: s = +1. Only one broadcast constant (C = 1/sqrt(2)).
template<bool INV>
__device__ __forceinline__ void dft8p(u64* zr, u64* zi) {
    const u64 CC = pbc(0.70710678118654752440f);

    // even quad (0,4,2,6)
    u64 e0r = padd(zr[0], zr[4]), e0i = padd(zi[0], zi[4]);
    u64 e1r = psub(zr[0], zr[4]), e1i = psub(zi[0], zi[4]);
    u64 e2r = padd(zr[2], zr[6]), e2i = padd(zi[2], zi[6]);
    u64 e3r = psub(zr[2], zr[6]), e3i = psub(zi[2], zi[6]);
    u64 E0r = padd(e0r, e2r), E0i = padd(e0i, e2i);
    u64 E2r = psub(e0r, e2r), E2i = psub(e0i, e2i);
    u64 E1r, E1i, E3r, E3i;
    if (!INV) {   // E1 = e1 - i*e3 ; E3 = e1 + i*e3
        E1r = padd(e1r, e3i); E1i = psub(e1i, e3r);
        E3r = psub(e1r, e3i); E3i = padd(e1i, e3r);
    } else {      // E1 = e1 + i*e3 ; E3 = e1 - i*e3
        E1r = psub(e1r, e3i); E1i = padd(e1i, e3r);
        E3r = padd(e1r, e3i); E3i = psub(e1i, e3r);
    }

    // odd quad (1,5,3,7)
    u64 o0r = padd(zr[1], zr[5]), o0i = padd(zi[1], zi[5]);
    u64 o1r = psub(zr[1], zr[5]), o1i = psub(zi[1], zi[5]);
    u64 o2r = padd(zr[3], zr[7]), o2i = padd(zi[3], zi[7]);
    u64 o3r = psub(zr[3], zr[7]), o3i = psub(zi[3], zi[7]);
    u64 O0r = padd(o0r, o2r), O0i = padd(o0i, o2i);
    u64 O2r = psub(o0r, o2r), O2i = psub(o0i, o2i);
    u64 O1r, O1i, O3r, O3i;
    if (!INV) {
        O1r = padd(o1r, o3i); O1i = psub(o1i, o3r);
        O3r = psub(o1r, o3i); O3i = padd(o1i, o3r);
    } else {
        O1r = psub(o1r, o3i); O1i = padd(o1i, o3r);
        O3r = padd(o1r, o3i); O3i = psub(o1i, o3r);
    }

    // k=0,4: z = E0 +/- O0
    zr[0] = padd(E0r, O0r); zi[0] = padd(E0i, O0i);
    zr[4] = psub(E0r, O0r); zi[4] = psub(E0i, O0i);

    // k=1,5: w8^s1 * O1; fwd w = C(1 - i): wO = C(O1r+O1i) + iC(O1i-O1r)
    //                     inv w = C(1 + i): wO = C(O1r-O1i) + iC(O1r+O1i)
    {
        u64 w1r, w1i;
        if (!INV) { w1r = pmul(CC, padd(O1r, O1i)); w1i = pmul(CC, psub(O1i, O1r)); }
        else      { w1r = pmul(CC, psub(O1r, O1i)); w1i = pmul(CC, padd(O1r, O1i)); }
        zr[1] = padd(E1r, w1r); zi[1] = padd(E1i, w1i);
        zr[5] = psub(E1r, w1r); zi[5] = psub(E1i, w1i);
    }

    // k=2,6: w = -s*i: fwd (-i)O2 = (O2i, -O2r); inv (i)O2 = (-O2i, O2r)
    if (!INV) {
        zr[2] = padd(E2r, O2i); zi[2] = psub(E2i, O2r);
        zr[6] = psub(E2r, O2i); zi[6] = padd(E2i, O2r);
    } else {
        zr[2] = psub(E2r, O2i); zi[2] = padd(E2i, O2r);
        zr[6] = padd(E2r, O2i); zi[6] = psub(E2i, O2r);
    }

    // k=3,7: fwd w = C(-1 - i): wO = C(O3i-O3r) - iC(O3r+O3i)
    //        inv w = C(-1 + i): wO = -C(O3r+O3i) + iC(O3r-O3i)
    {
        if (!INV) {
            u64 w3r = pmul(CC, psub(O3i, O3r));
            u64 t3  = pmul(CC, padd(O3r, O3i));
            zr[3] = padd(E3r, w3r); zi[3] = psub(E3i, t3);
            zr[7] = psub(E3r, w3r); zi[7] = padd(E3i, t3);
        } else {
            u64 t3  = pmul(CC, padd(O3r, O3i));
            u64 w3i = pmul(CC, psub(O3r, O3i));
            zr[3] = psub(E3r, t3); zi[3] = padd(E3i, w3i);
            zr[7] = padd(E3r, t3); zi[7] = psub(E3i, w3i);
        }
    }
}

// Twiddle by W^j (conj for INV) and store {re,im} as one 16B element; scalar
// power table built once with a log-depth chain, broadcast at use.
template<bool INV>
__device__ __forceinline__ void tw_storep(ulonglong2* __restrict__ buf,
                                          const u64* zr, const u64* zi,
                                          float2 w, int base, int stride) {
    buf[base] = make_ulonglong2(zr[0], zi[0]);
    float2 cs[8];
    cs[1] = w;
    cs[2] = cmulf(w, w);
    cs[3] = cmulf(cs[2], w);
    cs[4] = cmulf(cs[2], cs[2]);
    cs[5] = cmulf(cs[4], w);
    cs[6] = cmulf(cs[4], cs[2]);
    cs[7] = cmulf(cs[4], cs[3]);
#pragma unroll
    for (int j = 1; j < 8; j++) {
        float cr = cs[j].x;
        float ci = INV ? -cs[j].y : cs[j].y;
        u64 R = pbc(cr);
        u64 I = pbc(ci);
        int idx = base + stride * j;
        buf[idx] = make_ulonglong2(psub(pmul(zr[j], R), pmul(zi[j], I)),   // re
                                   pfma(zr[j], I, pmul(zi[j], R)));        // im
    }
}

__device__ __forceinline__ void loadp(u64* zr, u64* zi,
                                      const ulonglong2* __restrict__ buf, int ub) {
#pragma unroll
    for (int j = 0; j < 8; j++) {
        ulonglong2 v = buf[ub + 72 * j];
        zr[j] = v.x;
        zi[j] = v.y;
    }
}

__global__ void __launch_bounds__(THREADS, 12)
fft_conv_kernel(const float* __restrict__ x, float* __restrict__ out) {
    __shared__ ulonglong2 sP[PADN];   // ping: {packed re, packed im}
    __shared__ ulonglong2 sQ[PADN];   // pong

    int u = threadIdx.x;
    int ub = u + (u >> 3);
    int p = u >> 3, q = u & 7;

    float2 w1, w2;
    sincospif(-(float)u * (1.0f / 256.0f), &w1.y, &w1.x);   // e^{-2pi i u/512}
    sincospif(-(float)p * (1.0f / 32.0f),  &w2.y, &w2.x);   // e^{-2pi i p/64}

    int base = blockIdx.x * (4 * NW);   // 4 rows per block
    const float* xA0 = x + base;
    const float* xA1 = xA0 + NW;
    const float* xB0 = xA0 + 2 * NW;
    const float* xB1 = xA0 + 3 * NW;

    // Packed registers: lane0 = FFT A (rows 0,1), lane1 = FFT B (rows 2,3).
    u64 zr[8], zi[8];
#pragma unroll
    for (int j = 0; j < 8; j++) {
        int g = u + 64 * j;
        zr[j] = pk2(__ldg(xA0 + g), __ldg(xB0 + g));
        zi[j] = pk2(__ldg(xA1 + g), __ldg(xB1 + g));
    }

    // ---- forward ----
    dft8p<false>(zr, zi);
    tw_storep<false>(sP, zr, zi, w1, 9 * u, 1);
    __syncthreads();

    loadp(zr, zi, sP, ub);
    dft8p<false>(zr, zi);
    tw_storep<false>(sQ, zr, zi, w2, q + 72 * p, 9);
    __syncthreads();

    loadp(zr, zi, sQ, ub);
    dft8p<false>(zr, zi);               // natural order: reg j = bin u+64j

    // ---- spectrum multiply by real M (broadcast to both lanes) ----
#pragma unroll
    for (int j = 0; j < 8; j++) {
        u64 m = pbc(__ldg(&d_M[u + 64 * j]));
        zr[j] = pmul(zr[j], m);
        zi[j] = pmul(zi[j], m);
    }

    // ---- inverse ---- (ping-pong: sP reads all completed before sync2)
    dft8p<true>(zr, zi);
    tw_storep<true>(sP, zr, zi, w1, 9 * u, 1);
    __syncthreads();

    loadp(zr, zi, sP, ub);
    dft8p<true>(zr, zi);
    tw_storep<true>(sQ, zr, zi, w2, q + 72 * p, 9);
    __syncthreads();

    loadp(zr, zi, sQ, ub);
    dft8p<true>(zr, zi);

    float* oA0 = out + base;
    float* oA1 = oA0 + NW;
    float* oB0 = oA0 + 2 * NW;
    float* oB1 = oA0 + 3 * NW;
#pragma unroll
    for (int j = 0; j < 8; j++) {
        int g = u + 64 * j;
        float a, b;
        upk2(zr[j], a, b);
        oA0[g] = a;
        oB0[g] = b;
        upk2(zi[j], a, b);
        oA1[g] = a;
        oB1[g] = b;
    }
}

extern "C" void kernel_launch(void* const* d_in, const int* in_sizes, int n_in,
                              void* d_out, int out_size) {
    const float* x = (const float*)d_in[0];
    const float* w = (const float*)d_in[1];
    if (n_in >= 2 && in_sizes[0] < in_sizes[1]) {   // defensive: x is the big one
        const float* t = x; x = w; w = t;
    }
    float* out = (float*)d_out;

    compute_M_kernel<<<8, 64>>>(w);   // spread MUFU work over 8 SMs

    int rows = out_size / NW;        // 16384
    int blocks = rows / 4;           // 4096 (4 rows per block)
    fft_conv_kernel<<<blocks, THREADS>>>(x, out);
}